// round 15
// baseline (speedup 1.0000x reference)
#include <cuda_runtime.h>
#include <cuda_bf16.h>
#include <cstdint>

static constexpr int NG      = 2500;
static constexpr int NT      = 20000;
static constexpr int NE      = 640000;
static constexpr int SRC_DIM = 128;
static constexpr int DST_DIM = 500;
static constexpr int HID     = 128;
static constexpr int OUTD    = 128;
static constexpr int NCLS    = 16;

// ---------------- scratch (device globals: no allocation allowed) ----------------
__device__ int   g_deg[NT];          // zero-init at load; re-zeroed by k_scan each run
__device__ int   g_rowptr[NT + 1];
__device__ int   g_cursor[NT];
__device__ int   g_colidx[NE];
// weights as bf16 hi/lo planes: [w(6)][plane(2)][n(128)][k(512 padded)]
__device__ __nv_bfloat16 g_wtb[6 * 2 * 128 * 512];
// agg as bf16 hi/lo planes, plane-major (written by k_fused's in-kernel gather)
__device__ __nv_bfloat16 g_aggb[2 * NT * 128];

static constexpr size_t WST = (size_t)2 * 128 * 512;   // weight slot stride (elements)

__device__ __forceinline__ uint32_t bf2pack(float x, float y) {
    __nv_bfloat162 p = __halves2bfloat162(__float2bfloat16_rn(x), __float2bfloat16_rn(y));
    return *(uint32_t*)&p;
}

// ---------------- k_trh: weight transpose + bf16 split + edge histogram ----------------
__global__ void k_trh(const float* __restrict__ W1s, const float* __restrict__ W1n,
                      const float* __restrict__ W2s, const float* __restrict__ W2n,
                      const float* __restrict__ Wc1, const float* __restrict__ Wc2,
                      const int* __restrict__ edst) {
    int t = blockIdx.x * blockDim.x + threadIdx.x;
    int e0 = t * 2;
    if (e0 < NE)     atomicAdd(&g_deg[__ldg(&edst[e0])], 1);
    if (e0 + 1 < NE) atomicAdd(&g_deg[__ldg(&edst[e0 + 1])], 1);

    if (t >= 6 * 65536) return;
    int w   = t >> 16;
    int rem = t & 65535;
    int n   = rem >> 9;
    int k   = rem & 511;
    float v = 0.f;
    if (w == 0)      { if (k < DST_DIM) v = W1s[(size_t)k * 128 + n]; }
    else if (w == 1) { if (k < 128)     v = W1n[(size_t)k * 128 + n]; }
    else if (w == 2) { if (k < 128)     v = W2s[(size_t)k * 128 + n]; }
    else if (w == 3) { if (k < 128)     v = W2n[(size_t)k * 128 + n]; }
    else if (w == 4) { if (k < 128)     v = Wc1[(size_t)k * 128 + n]; }
    else             { if (k < 128 && n < NCLS) v = Wc2[(size_t)k * NCLS + n]; }
    __nv_bfloat16 hb = __float2bfloat16_rn(v);
    float lo = v - __bfloat162float(hb);
    g_wtb[(size_t)w * WST + (size_t)n * 512 + k] = hb;
    g_wtb[(size_t)w * WST + 128 * 512 + (size_t)n * 512 + k] = __float2bfloat16_rn(lo);
}

// ---------------- single-pass scan (also re-zeros g_deg for the next replay) ----------------
__global__ void __launch_bounds__(1024) k_scan() {
    constexpr int PER = 20;
    __shared__ int wsum[32];
    const int tid  = threadIdx.x;
    const int lane = tid & 31;
    const int wid  = tid >> 5;
    const int base = tid * PER;

    int pref[PER];
    int s = 0;
    #pragma unroll
    for (int q = 0; q < PER; ++q) {
        int i = base + q;
        int d = 0;
        if (i < NT) { d = g_deg[i]; g_deg[i] = 0; }
        pref[q] = s;
        s += d;
    }
    int x = s;
    #pragma unroll
    for (int off = 1; off < 32; off <<= 1) {
        int y = __shfl_up_sync(0xffffffffu, x, off);
        if (lane >= off) x += y;
    }
    if (lane == 31) wsum[wid] = x;
    __syncthreads();
    if (wid == 0) {
        int w = wsum[lane];
        #pragma unroll
        for (int off = 1; off < 32; off <<= 1) {
            int y = __shfl_up_sync(0xffffffffu, w, off);
            if (lane >= off) w += y;
        }
        wsum[lane] = w;
    }
    __syncthreads();
    const int tbase = (x - s) + (wid ? wsum[wid - 1] : 0);
    #pragma unroll
    for (int q = 0; q < PER; ++q) {
        int i = base + q;
        if (i < NT) {
            int rp = tbase + pref[q];
            g_rowptr[i] = rp;
            g_cursor[i] = rp;
        }
    }
    if (tid == 1023) g_rowptr[NT] = tbase + s;
}

// 8 edges per thread: independent atomic chains raise MLP
__global__ void k_scatter(const int* __restrict__ src, const int* __restrict__ dst) {
    int e0 = (blockIdx.x * blockDim.x + threadIdx.x) * 8;
    #pragma unroll
    for (int q = 0; q < 8; ++q) {
        int e = e0 + q;
        if (e < NE) {
            int p = atomicAdd(&g_cursor[__ldg(&dst[e])], 1);
            g_colidx[p] = __ldg(&src[e]);
        }
    }
}

// ---------------- fused: SpMM + 4-layer network, 64-row tiles, 2 CTAs/SM ----------------
static constexpr int MT      = 64;                 // rows per CTA
static constexpr int SP      = 40;                 // bf16 tile pitch (80B, conflict-free)
static constexpr int PLANE_A = MT * SP * 2;        // 5120 B
static constexpr int PLANE_B = 128 * SP * 2;       // 10240 B
static constexpr int OFF_H   = 0;                              // H[ch(4)][plane(2)]
static constexpr int OFF_AST = OFF_H + 8 * PLANE_A;            // 40960: Ast[s(2)][plane(2)]
static constexpr int OFF_BS  = OFF_AST + 4 * PLANE_A;          // 61440: Bs[s(2)][plane(2)]
static constexpr int OFF_AFP = OFF_BS + 4 * PLANE_B;           // 102400: fp32 64 x 36
static constexpr int SMEM_FUSED = OFF_AFP + MT * 144;          // 111616 -> 2 CTAs/SM

__device__ __forceinline__ uint32_t smem_u32(const void* p) {
    uint32_t a;
    asm("{ .reg .u64 t; cvta.to.shared.u64 t, %1; cvt.u32.u64 %0, t; }" : "=r"(a) : "l"(p));
    return a;
}
#define CP16(dst, src) \
    asm volatile("cp.async.ca.shared.global [%0], [%1], 16;" :: "r"(dst), "l"(src))
#define CP16Z(dst, src, nb) \
    asm volatile("cp.async.ca.shared.global [%0], [%1], 16, %2;" :: "r"(dst), "l"(src), "r"(nb))
#define CP16CG(dst, src, nb) \
    asm volatile("cp.async.cg.shared.global [%0], [%1], 16, %2;" :: "r"(dst), "l"(src), "r"(nb))
#define CP_COMMIT() asm volatile("cp.async.commit_group;" ::: "memory")
#define CP_WAITG1() asm volatile("cp.async.wait_group 1;" ::: "memory")
#define CP_WAIT0()  asm volatile("cp.async.wait_group 0;" ::: "memory")

__device__ __forceinline__ void mma16816(float* c, const uint32_t* a, const uint32_t* b) {
    asm volatile(
        "mma.sync.aligned.m16n8k16.row.col.f32.bf16.bf16.f32 "
        "{%0,%1,%2,%3}, {%4,%5,%6,%7}, {%8,%9}, {%0,%1,%2,%3};"
        : "+f"(c[0]), "+f"(c[1]), "+f"(c[2]), "+f"(c[3])
        : "r"(a[0]), "r"(a[1]), "r"(a[2]), "r"(a[3]), "r"(b[0]), "r"(b[1]));
}
__device__ __forceinline__ void ldsm4(uint32_t& r0, uint32_t& r1, uint32_t& r2, uint32_t& r3,
                                      uint32_t addr) {
    asm volatile("ldmatrix.sync.aligned.m8n8.x4.shared.b16 {%0,%1,%2,%3}, [%4];"
                 : "=r"(r0), "=r"(r1), "=r"(r2), "=r"(r3) : "r"(addr));
}

// chunk modes
struct Desc {
    int mode;                    // 0=H, 1=train fp32 (convert), 2=agg bf16 direct
    int k0; int hch;
    const __nv_bfloat16* B; int bk0;
};
__device__ __forceinline__ Desc mkdesc(int j, const __nv_bfloat16* wtb) {
    Desc d; d.mode = 0; d.k0 = 0; d.hch = 0;
    if (j < 16)      { d.mode = 1; d.k0 = j * 32;        d.B = wtb + 0 * WST; d.bk0 = j * 32; }
    else if (j < 20) { d.mode = 2; d.k0 = (j - 16) * 32; d.B = wtb + 1 * WST; d.bk0 = (j - 16) * 32; }
    else if (j < 24) { d.hch = j - 20; d.B = wtb + 2 * WST; d.bk0 = (j - 20) * 32; }
    else if (j < 28) { d.mode = 2; d.k0 = (j - 24) * 32; d.B = wtb + 3 * WST; d.bk0 = (j - 24) * 32; }
    else if (j < 32) { d.hch = j - 28; d.B = wtb + 4 * WST; d.bk0 = (j - 28) * 32; }
    else             { d.hch = j - 32; d.B = wtb + 5 * WST; d.bk0 = (j - 32) * 32; }
    return d;
}

// warp tile 32x64 via ldmatrix
template <int NJJ>
__device__ __forceinline__ void mma_chunk(uint32_t Ab, uint32_t Bb,
                                          int warp_m, int warp_n, int lane,
                                          float (&c)[2][8][4]) {
    const uint32_t a_lane = Ab + (warp_m * 32 + (lane & 15)) * 80 + (lane >> 4) * 16;
    const uint32_t b_lane = Bb + (warp_n * 64 + (lane & 15)) * 80 + (lane >> 4) * 16;
    #pragma unroll
    for (int term = 0; term < 3; ++term) {
        const uint32_t at = a_lane + (term == 2 ? PLANE_A : 0);
        const uint32_t bt = b_lane + (term == 1 ? PLANE_B : 0);
        #pragma unroll
        for (int h = 0; h < 2; ++h) {
            const uint32_t ah = at + h * 32;
            const uint32_t bh = bt + h * 32;
            uint32_t a[2][4], b[NJJ][2];
            ldsm4(a[0][0], a[0][1], a[0][2], a[0][3], ah);
            ldsm4(a[1][0], a[1][1], a[1][2], a[1][3], ah + 16 * 80);
            #pragma unroll
            for (int jp = 0; jp < NJJ / 2; ++jp)
                ldsm4(b[2 * jp][0], b[2 * jp + 1][0], b[2 * jp][1], b[2 * jp + 1][1],
                      bh + jp * 16 * 80);
            #pragma unroll
            for (int i = 0; i < 2; ++i)
                #pragma unroll
                for (int jj = 0; jj < NJJ; ++jj)
                    mma16816(c[i][jj], a[i], b[jj]);
        }
    }
}

// epilogue: relu(c+bias) -> bf16 hi/lo H tiles; clears c
__device__ __forceinline__ void epi_to_H(float (&c)[2][8][4], const float* bias,
                                         char* smem, int warp_m, int warp_n, int lane) {
    __syncthreads();
    #pragma unroll
    for (int i = 0; i < 2; ++i) {
        #pragma unroll
        for (int jj = 0; jj < 8; ++jj) {
            int col = warp_n * 64 + jj * 8 + (lane & 3) * 2;
            int ch = col >> 5, kk = col & 31;
            float b0 = __ldg(&bias[col]), b1 = __ldg(&bias[col + 1]);
            #pragma unroll
            for (int rh = 0; rh < 2; ++rh) {
                int row = warp_m * 32 + i * 16 + (lane >> 2) + rh * 8;
                float v0 = fmaxf(c[i][jj][rh * 2 + 0] + b0, 0.f);
                float v1 = fmaxf(c[i][jj][rh * 2 + 1] + b1, 0.f);
                float l0 = v0 - __bfloat162float(__float2bfloat16_rn(v0));
                float l1 = v1 - __bfloat162float(__float2bfloat16_rn(v1));
                *(uint32_t*)(smem + OFF_H + (ch * 2 + 0) * PLANE_A + (row * SP + kk) * 2) = bf2pack(v0, v1);
                *(uint32_t*)(smem + OFF_H + (ch * 2 + 1) * PLANE_A + (row * SP + kk) * 2) = bf2pack(l0, l1);
                c[i][jj][rh * 2 + 0] = 0.f;
                c[i][jj][rh * 2 + 1] = 0.f;
            }
        }
    }
}

__global__ void __launch_bounds__(128, 2) k_fused(
    const float* __restrict__ gene, const float* __restrict__ train,
    __nv_bfloat16* __restrict__ aggb, const __nv_bfloat16* __restrict__ wtb,
    const float* __restrict__ b1, const float* __restrict__ b2,
    const float* __restrict__ bc1, const float* __restrict__ bc2,
    float* __restrict__ outp)
{
    extern __shared__ __align__(16) char smem[];
    const int tid    = threadIdx.x;
    const int lane   = tid & 31;
    const int wid    = tid >> 5;
    const int warp_m = wid >> 1;
    const int warp_n = wid & 1;
    const int m0     = blockIdx.x * MT;

    const uint32_t sb    = smem_u32(smem);
    const uint32_t ast_u = sb + OFF_AST;
    const uint32_t bs_u  = sb + OFF_BS;
    const uint32_t afp_u = sb + OFF_AFP;
    float* Afp = (float*)(smem + OFF_AFP);

    float c[2][8][4];
    #pragma unroll
    for (int i = 0; i < 2; ++i)
        #pragma unroll
        for (int j = 0; j < 8; ++j)
            #pragma unroll
            for (int q = 0; q < 4; ++q) c[i][j][q] = 0.f;

    // ---- in-kernel SpMM: gather one agg row (warp-collective), write bf16 planes ----
    auto gather_row = [&](int rlocal) {
        int gr = m0 + rlocal;
        if (gr >= NT) return;
        int beg = g_rowptr[gr];
        int end = g_rowptr[gr + 1];
        float4 acc = make_float4(0.f, 0.f, 0.f, 0.f);
        for (int base = beg; base < end; base += 32) {
            int e = base + lane;
            int myidx = (e < end) ? g_colidx[e] : 0;
            int cnt = min(32, end - base);
            int q = 0;
            for (; q + 8 <= cnt; q += 8) {
                float4 v[8];
                #pragma unroll
                for (int u = 0; u < 8; ++u) {
                    int s = __shfl_sync(0xffffffffu, myidx, q + u);
                    v[u] = *((const float4*)(gene + (size_t)s * SRC_DIM) + lane);
                }
                #pragma unroll
                for (int u = 0; u < 8; ++u) {
                    acc.x += v[u].x; acc.y += v[u].y; acc.z += v[u].z; acc.w += v[u].w;
                }
            }
            for (; q < cnt; ++q) {
                int s = __shfl_sync(0xffffffffu, myidx, q);
                float4 v = *((const float4*)(gene + (size_t)s * SRC_DIM) + lane);
                acc.x += v.x; acc.y += v.y; acc.z += v.z; acc.w += v.w;
            }
        }
        float inv = 1.0f / (float)max(end - beg, 1);
        acc.x *= inv; acc.y *= inv; acc.z *= inv; acc.w *= inv;
        float lx = acc.x - __bfloat162float(__float2bfloat16_rn(acc.x));
        float ly = acc.y - __bfloat162float(__float2bfloat16_rn(acc.y));
        float lz = acc.z - __bfloat162float(__float2bfloat16_rn(acc.z));
        float lw = acc.w - __bfloat162float(__float2bfloat16_rn(acc.w));
        size_t off = (size_t)gr * 128 + lane * 4;
        *(uint2*)(aggb + off)                    = make_uint2(bf2pack(acc.x, acc.y), bf2pack(acc.z, acc.w));
        *(uint2*)(aggb + (size_t)NT * 128 + off) = make_uint2(bf2pack(lx, ly), bf2pack(lz, lw));
        __threadfence_block();
    };

    // B loads for chunk cj into stage (always commits one group)
    auto issue_B = [&](int cj, int stage) {
        Desc d = mkdesc(cj, wtb);
        #pragma unroll
        for (int p = 0; p < 2; ++p) {
            const __nv_bfloat16* bp = d.B + (size_t)p * 128 * 512;
            uint32_t bd = bs_u + (stage * 2 + p) * PLANE_B;
            #pragma unroll
            for (int i = 0; i < 4; ++i) {
                int idx = i * 128 + tid;
                int n = idx >> 2, cc = idx & 3;
                CP16(bd + n * 80 + cc * 16, bp + (size_t)n * 512 + d.bk0 + cc * 8);
            }
        }
        CP_COMMIT();
    };
    // A loads for chunk cj (always commits one group, possibly empty)
    auto issue_A = [&](int cj, int stage) {
        Desc d = mkdesc(cj, wtb);
        if (d.mode == 1) {
            #pragma unroll
            for (int i = 0; i < 4; ++i) {
                int idx = i * 128 + tid;
                int row = idx >> 3, cc = idx & 7;
                int gr = m0 + row, k = d.k0 + cc * 4;
                int nb = 0;
                if (gr < NT) { int rem = DST_DIM - k; nb = (rem >= 4) ? 16 : (rem > 0 ? rem * 4 : 0); }
                const float* src = nb ? (train + (size_t)gr * DST_DIM + k) : train;
                CP16Z(afp_u + row * 144 + cc * 16, src, nb);
            }
        } else if (d.mode == 2) {
            // agg planes (written by this CTA's gathers) -> Ast, via L2 (.cg)
            #pragma unroll
            for (int i = 0; i < 4; ++i) {
                int idx = i * 128 + tid;
                int plane = idx >> 8;
                int rem = idx & 255;
                int row = rem >> 2, cc = rem & 3;
                int gr = m0 + row;
                uint32_t dst = ast_u + (stage * 2 + plane) * PLANE_A + row * 80 + cc * 16;
                const __nv_bfloat16* src =
                    aggb + (size_t)plane * NT * 128 + (size_t)gr * 128 + d.k0 + cc * 8;
                int nb = (gr < NT) ? 16 : 0;
                CP16CG(dst, nb ? src : (const __nv_bfloat16*)aggb, nb);
            }
        }
        CP_COMMIT();
    };

    // prologue: chunk 0 issued, then first 4 agg rows gathered (loads overlap)
    issue_B(0, 0);
    issue_A(0, 0);
    gather_row(wid);

    for (int j = 0; j < 36; ++j) {
        const int s = j & 1;
        Desc d = mkdesc(j, wtb);

        if (j + 1 < 36) issue_B(j + 1, s ^ 1);

        if (j + 1 < 36) { CP_WAITG1(); } else { CP_WAIT0(); }
        __syncthreads();

        // convert fp32 staging -> bf16 hi/lo Ast[s] (train chunks; 2 threads/row)
        if (d.mode == 1) {
            {
                int row = tid >> 1, half = tid & 1;
                __nv_bfloat16* Ah = (__nv_bfloat16*)(smem + OFF_AST + (s * 2 + 0) * PLANE_A);
                __nv_bfloat16* Al = (__nv_bfloat16*)(smem + OFF_AST + (s * 2 + 1) * PLANE_A);
                const float* ar = Afp + row * 36 + half * 16;
                uint32_t hp[8], lp[8];
                #pragma unroll
                for (int cc = 0; cc < 4; ++cc) {
                    float4 f = *(const float4*)(ar + cc * 4);
                    float l0 = f.x - __bfloat162float(__float2bfloat16_rn(f.x));
                    float l1 = f.y - __bfloat162float(__float2bfloat16_rn(f.y));
                    float l2 = f.z - __bfloat162float(__float2bfloat16_rn(f.z));
                    float l3 = f.w - __bfloat162float(__float2bfloat16_rn(f.w));
                    hp[cc * 2 + 0] = bf2pack(f.x, f.y);
                    hp[cc * 2 + 1] = bf2pack(f.z, f.w);
                    lp[cc * 2 + 0] = bf2pack(l0, l1);
                    lp[cc * 2 + 1] = bf2pack(l2, l3);
                }
                uint32_t* dh = (uint32_t*)(Ah + row * SP + half * 16);
                uint32_t* dl = (uint32_t*)(Al + row * SP + half * 16);
                #pragma unroll
                for (int cc = 0; cc < 2; ++cc) {
                    *(uint4*)(dh + cc * 4) = *(uint4*)(hp + cc * 4);
                    *(uint4*)(dl + cc * 4) = *(uint4*)(lp + cc * 4);
                }
            }
            __syncthreads();   // Ast[s] ready; AFP free for next issue_A
        }

        if (j + 1 < 36) issue_A(j + 1, s ^ 1);

        const uint32_t Ab = (d.mode != 0) ? (ast_u + s * 2 * PLANE_A)
                                          : (sb + OFF_H + d.hch * 2 * PLANE_A);
        const uint32_t Bb = bs_u + s * 2 * PLANE_B;
        if (j < 32)           mma_chunk<8>(Ab, Bb, warp_m, warp_n, lane, c);
        else if (warp_n == 0) mma_chunk<2>(Ab, Bb, warp_m, warp_n, lane, c);

        if (j == 19)      epi_to_H(c, b1, smem, warp_m, warp_n, lane);
        else if (j == 27) epi_to_H(c, b2, smem, warp_m, warp_n, lane);
        else if (j == 31) epi_to_H(c, bc1, smem, warp_m, warp_n, lane);

        // in-kernel SpMM: rows 4..63 over iterations 0..14 (done before issue_A(16))
        if (j < 15) gather_row((j + 1) * 4 + wid);

        __syncthreads();   // protect stage s for the early issue at top of j+1
    }

    // ---- cls store: out[NT,16] = c + bc2 (warp_n==0 warps hold cols 0..15) ----
    if (warp_n == 0) {
        #pragma unroll
        for (int i = 0; i < 2; ++i) {
            #pragma unroll
            for (int jj = 0; jj < 2; ++jj) {
                int col = jj * 8 + (lane & 3) * 2;
                float b0 = __ldg(&bc2[col]), b1 = __ldg(&bc2[col + 1]);
                #pragma unroll
                for (int rh = 0; rh < 2; ++rh) {
                    int row = m0 + warp_m * 32 + i * 16 + (lane >> 2) + rh * 8;
                    if (row < NT) {
                        float2 v = make_float2(c[i][jj][rh * 2 + 0] + b0,
                                               c[i][jj][rh * 2 + 1] + b1);
                        *(float2*)(outp + (size_t)row * NCLS + col) = v;
                    }
                }
            }
        }
    }
}

// ---------------- launch ----------------
extern "C" void kernel_launch(void* const* d_in, const int* in_sizes, int n_in,
                              void* d_out, int out_size)
{
    const float* gene  = (const float*)d_in[0];
    const float* train = (const float*)d_in[1];
    const int*   esrc  = (const int*)  d_in[2];
    const int*   edst  = (const int*)  d_in[3];
    const float* W1n   = (const float*)d_in[4];
    const float* W1s   = (const float*)d_in[5];
    const float* b1    = (const float*)d_in[6];
    const float* W2n   = (const float*)d_in[7];
    const float* W2s   = (const float*)d_in[8];
    const float* b2    = (const float*)d_in[9];
    const float* Wc1   = (const float*)d_in[10];
    const float* bc1   = (const float*)d_in[11];
    const float* Wc2   = (const float*)d_in[12];
    const float* bc2   = (const float*)d_in[13];
    float* out = (float*)d_out;

    __nv_bfloat16 *wtb, *aggb;
    cudaGetSymbolAddress((void**)&wtb,  g_wtb);
    cudaGetSymbolAddress((void**)&aggb, g_aggb);

    static bool attr_done = false;
    if (!attr_done) {
        cudaFuncSetAttribute(k_fused, cudaFuncAttributeMaxDynamicSharedMemorySize, SMEM_FUSED);
        cudaFuncSetAttribute(k_fused, cudaFuncAttributePreferredSharedMemoryCarveout,
                             cudaSharedmemCarveoutMaxShared);
        attr_done = true;
    }

    k_trh<<<(6 * 65536 + 255) / 256, 256>>>(W1s, W1n, W2s, W2n, Wc1, Wc2, edst);
    k_scan<<<1, 1024>>>();
    k_scatter<<<(NE / 8 + 255) / 256, 256>>>(esrc, edst);
    k_fused<<<(NT + MT - 1) / MT, 128, SMEM_FUSED>>>(gene, train, aggb, wtb,
                                                     b1, b2, bc1, bc2, out);

    (void)in_sizes; (void)n_in; (void)out_size;
}

// round 16
// speedup vs baseline: 1.3559x; 1.3559x over previous
#include <cuda_runtime.h>
#include <cuda_bf16.h>
#include <cstdint>

static constexpr int NG      = 2500;
static constexpr int NT      = 20000;
static constexpr int NE      = 640000;
static constexpr int SRC_DIM = 128;
static constexpr int DST_DIM = 500;
static constexpr int HID     = 128;
static constexpr int OUTD    = 128;
static constexpr int NCLS    = 16;

// ---------------- scratch (device globals: no allocation allowed) ----------------
__device__ int   g_deg[NT];          // zero-init at load; re-zeroed by k_scan each run
__device__ int   g_rowptr[NT + 1];
__device__ int   g_cursor[NT];
__device__ int   g_colidx[NE];
// weights as bf16 hi/lo planes: [w(6)][plane(2)][n(128)][k(512 padded)]
__device__ __nv_bfloat16 g_wtb[6 * 2 * 128 * 512];
// agg as bf16 hi/lo planes, plane-major (written by k_spmm epilogue)
__device__ __nv_bfloat16 g_aggb[2 * NT * 128];

static constexpr size_t WST = (size_t)2 * 128 * 512;   // weight slot stride (elements)

__device__ __forceinline__ uint32_t bf2pack(float x, float y) {
    __nv_bfloat162 p = __halves2bfloat162(__float2bfloat16_rn(x), __float2bfloat16_rn(y));
    return *(uint32_t*)&p;
}

// ---------------- k_trh: weight transpose + bf16 split + edge histogram ----------------
__global__ void k_trh(const float* __restrict__ W1s, const float* __restrict__ W1n,
                      const float* __restrict__ W2s, const float* __restrict__ W2n,
                      const float* __restrict__ Wc1, const float* __restrict__ Wc2,
                      const int* __restrict__ edst) {
    int t = blockIdx.x * blockDim.x + threadIdx.x;
    int e0 = t * 2;
    if (e0 < NE)     atomicAdd(&g_deg[__ldg(&edst[e0])], 1);
    if (e0 + 1 < NE) atomicAdd(&g_deg[__ldg(&edst[e0 + 1])], 1);

    if (t >= 6 * 65536) return;
    int w   = t >> 16;
    int rem = t & 65535;
    int n   = rem >> 9;
    int k   = rem & 511;
    float v = 0.f;
    if (w == 0)      { if (k < DST_DIM) v = W1s[(size_t)k * 128 + n]; }
    else if (w == 1) { if (k < 128)     v = W1n[(size_t)k * 128 + n]; }
    else if (w == 2) { if (k < 128)     v = W2s[(size_t)k * 128 + n]; }
    else if (w == 3) { if (k < 128)     v = W2n[(size_t)k * 128 + n]; }
    else if (w == 4) { if (k < 128)     v = Wc1[(size_t)k * 128 + n]; }
    else             { if (k < 128 && n < NCLS) v = Wc2[(size_t)k * NCLS + n]; }
    __nv_bfloat16 hb = __float2bfloat16_rn(v);
    float lo = v - __bfloat162float(hb);
    g_wtb[(size_t)w * WST + (size_t)n * 512 + k] = hb;
    g_wtb[(size_t)w * WST + 128 * 512 + (size_t)n * 512 + k] = __float2bfloat16_rn(lo);
}

// ---------------- single-pass scan (also re-zeros g_deg for the next replay) ----------------
__global__ void __launch_bounds__(1024) k_scan() {
    constexpr int PER = 20;
    __shared__ int wsum[32];
    const int tid  = threadIdx.x;
    const int lane = tid & 31;
    const int wid  = tid >> 5;
    const int base = tid * PER;

    int pref[PER];
    int s = 0;
    #pragma unroll
    for (int q = 0; q < PER; ++q) {
        int i = base + q;
        int d = 0;
        if (i < NT) { d = g_deg[i]; g_deg[i] = 0; }
        pref[q] = s;
        s += d;
    }
    int x = s;
    #pragma unroll
    for (int off = 1; off < 32; off <<= 1) {
        int y = __shfl_up_sync(0xffffffffu, x, off);
        if (lane >= off) x += y;
    }
    if (lane == 31) wsum[wid] = x;
    __syncthreads();
    if (wid == 0) {
        int w = wsum[lane];
        #pragma unroll
        for (int off = 1; off < 32; off <<= 1) {
            int y = __shfl_up_sync(0xffffffffu, w, off);
            if (lane >= off) w += y;
        }
        wsum[lane] = w;
    }
    __syncthreads();
    const int tbase = (x - s) + (wid ? wsum[wid - 1] : 0);
    #pragma unroll
    for (int q = 0; q < PER; ++q) {
        int i = base + q;
        if (i < NT) {
            int rp = tbase + pref[q];
            g_rowptr[i] = rp;
            g_cursor[i] = rp;
        }
    }
    if (tid == 1023) g_rowptr[NT] = tbase + s;
}

// 8 edges per thread: independent atomic chains raise MLP
__global__ void k_scatter(const int* __restrict__ src, const int* __restrict__ dst) {
    int e0 = (blockIdx.x * blockDim.x + threadIdx.x) * 8;
    #pragma unroll
    for (int q = 0; q < 8; ++q) {
        int e = e0 + q;
        if (e < NE) {
            int p = atomicAdd(&g_cursor[__ldg(&dst[e])], 1);
            g_colidx[p] = __ldg(&src[e]);
        }
    }
}

// ---------------- SpMM mean: one warp per dst row; writes bf16 hi/lo planes ----------------
__global__ void __launch_bounds__(256) k_spmm(const float* __restrict__ gene) {
    int row  = (blockIdx.x * blockDim.x + threadIdx.x) >> 5;
    int lane = threadIdx.x & 31;
    if (row >= NT) return;
    int beg = g_rowptr[row];
    int end = g_rowptr[row + 1];
    float4 a = make_float4(0.f, 0.f, 0.f, 0.f);
    for (int base = beg; base < end; base += 32) {
        int myidx = (base + lane < end) ? g_colidx[base + lane] : 0;
        int cnt = min(32, end - base);
        int j = 0;
        for (; j + 4 <= cnt; j += 4) {
            int s0 = __shfl_sync(0xffffffffu, myidx, j);
            int s1 = __shfl_sync(0xffffffffu, myidx, j + 1);
            int s2 = __shfl_sync(0xffffffffu, myidx, j + 2);
            int s3 = __shfl_sync(0xffffffffu, myidx, j + 3);
            float4 v0 = *((const float4*)(gene + (size_t)s0 * SRC_DIM) + lane);
            float4 v1 = *((const float4*)(gene + (size_t)s1 * SRC_DIM) + lane);
            float4 v2 = *((const float4*)(gene + (size_t)s2 * SRC_DIM) + lane);
            float4 v3 = *((const float4*)(gene + (size_t)s3 * SRC_DIM) + lane);
            a.x += v0.x + v1.x + v2.x + v3.x;
            a.y += v0.y + v1.y + v2.y + v3.y;
            a.z += v0.z + v1.z + v2.z + v3.z;
            a.w += v0.w + v1.w + v2.w + v3.w;
        }
        for (; j < cnt; ++j) {
            int s = __shfl_sync(0xffffffffu, myidx, j);
            float4 v = *((const float4*)(gene + (size_t)s * SRC_DIM) + lane);
            a.x += v.x; a.y += v.y; a.z += v.z; a.w += v.w;
        }
    }
    float inv = 1.0f / (float)max(end - beg, 1);
    a.x *= inv; a.y *= inv; a.z *= inv; a.w *= inv;
    float lx = a.x - __bfloat162float(__float2bfloat16_rn(a.x));
    float ly = a.y - __bfloat162float(__float2bfloat16_rn(a.y));
    float lz = a.z - __bfloat162float(__float2bfloat16_rn(a.z));
    float lw = a.w - __bfloat162float(__float2bfloat16_rn(a.w));
    size_t off = (size_t)row * 128 + lane * 4;
    *(uint2*)(g_aggb + off)                    = make_uint2(bf2pack(a.x, a.y), bf2pack(a.z, a.w));
    *(uint2*)(g_aggb + (size_t)NT * 128 + off) = make_uint2(bf2pack(lx, ly), bf2pack(lz, lw));
}

// ---------------- fused 4-layer network, 64-row tiles, 256 threads, 2 CTAs/SM ----------------
static constexpr int MT      = 64;                 // rows per CTA
static constexpr int SP      = 40;                 // bf16 tile pitch (80B, conflict-free)
static constexpr int PLANE_A = MT * SP * 2;        // 5120 B
static constexpr int PLANE_B = 128 * SP * 2;       // 10240 B
static constexpr int OFF_H   = 0;                              // H[ch(4)][plane(2)]
static constexpr int OFF_AST = OFF_H + 8 * PLANE_A;            // 40960: Ast[s(2)][plane(2)]
static constexpr int OFF_BS  = OFF_AST + 4 * PLANE_A;          // 61440: Bs[s(2)][plane(2)]
static constexpr int OFF_AFP = OFF_BS + 4 * PLANE_B;           // 102400: fp32 64 x 36
static constexpr int SMEM_FUSED = OFF_AFP + MT * 144;          // 111616 -> 2 CTAs/SM

__device__ __forceinline__ uint32_t smem_u32(const void* p) {
    uint32_t a;
    asm("{ .reg .u64 t; cvta.to.shared.u64 t, %1; cvt.u32.u64 %0, t; }" : "=r"(a) : "l"(p));
    return a;
}
#define CP16(dst, src) \
    asm volatile("cp.async.ca.shared.global [%0], [%1], 16;" :: "r"(dst), "l"(src))
#define CP16Z(dst, src, nb) \
    asm volatile("cp.async.ca.shared.global [%0], [%1], 16, %2;" :: "r"(dst), "l"(src), "r"(nb))
#define CP_COMMIT() asm volatile("cp.async.commit_group;" ::: "memory")
#define CP_WAITG1() asm volatile("cp.async.wait_group 1;" ::: "memory")
#define CP_WAIT0()  asm volatile("cp.async.wait_group 0;" ::: "memory")

__device__ __forceinline__ void mma16816(float* c, const uint32_t* a, const uint32_t* b) {
    asm volatile(
        "mma.sync.aligned.m16n8k16.row.col.f32.bf16.bf16.f32 "
        "{%0,%1,%2,%3}, {%4,%5,%6,%7}, {%8,%9}, {%0,%1,%2,%3};"
        : "+f"(c[0]), "+f"(c[1]), "+f"(c[2]), "+f"(c[3])
        : "r"(a[0]), "r"(a[1]), "r"(a[2]), "r"(a[3]), "r"(b[0]), "r"(b[1]));
}
__device__ __forceinline__ void ldsm4(uint32_t& r0, uint32_t& r1, uint32_t& r2, uint32_t& r3,
                                      uint32_t addr) {
    asm volatile("ldmatrix.sync.aligned.m8n8.x4.shared.b16 {%0,%1,%2,%3}, [%4];"
                 : "=r"(r0), "=r"(r1), "=r"(r2), "=r"(r3) : "r"(addr));
}

// chunk modes
struct Desc {
    int mode;                    // 0=H, 1=train fp32 (convert), 2=agg bf16 direct
    int k0; int hch;
    const __nv_bfloat16* B; int bk0;
};
__device__ __forceinline__ Desc mkdesc(int j, const __nv_bfloat16* wtb) {
    Desc d; d.mode = 0; d.k0 = 0; d.hch = 0;
    if (j < 16)      { d.mode = 1; d.k0 = j * 32;        d.B = wtb + 0 * WST; d.bk0 = j * 32; }
    else if (j < 20) { d.mode = 2; d.k0 = (j - 16) * 32; d.B = wtb + 1 * WST; d.bk0 = (j - 16) * 32; }
    else if (j < 24) { d.hch = j - 20; d.B = wtb + 2 * WST; d.bk0 = (j - 20) * 32; }
    else if (j < 28) { d.mode = 2; d.k0 = (j - 24) * 32; d.B = wtb + 3 * WST; d.bk0 = (j - 24) * 32; }
    else if (j < 32) { d.hch = j - 28; d.B = wtb + 4 * WST; d.bk0 = (j - 28) * 32; }
    else             { d.hch = j - 32; d.B = wtb + 5 * WST; d.bk0 = (j - 32) * 32; }
    return d;
}

// warp tile 32x32 via ldmatrix (8 warps: warp_m in 0..1, warp_n in 0..3)
template <int NJJ>
__device__ __forceinline__ void mma_chunk(uint32_t Ab, uint32_t Bb,
                                          int warp_m, int warp_n, int lane,
                                          float (&c)[2][4][4]) {
    const uint32_t a_lane = Ab + (warp_m * 32 + (lane & 15)) * 80 + (lane >> 4) * 16;
    const uint32_t b_lane = Bb + (warp_n * 32 + (lane & 15)) * 80 + (lane >> 4) * 16;
    #pragma unroll
    for (int term = 0; term < 3; ++term) {
        const uint32_t at = a_lane + (term == 2 ? PLANE_A : 0);
        const uint32_t bt = b_lane + (term == 1 ? PLANE_B : 0);
        #pragma unroll
        for (int h = 0; h < 2; ++h) {
            const uint32_t ah = at + h * 32;
            const uint32_t bh = bt + h * 32;
            uint32_t a[2][4], b[NJJ][2];
            ldsm4(a[0][0], a[0][1], a[0][2], a[0][3], ah);
            ldsm4(a[1][0], a[1][1], a[1][2], a[1][3], ah + 16 * 80);
            #pragma unroll
            for (int jp = 0; jp < NJJ / 2; ++jp)
                ldsm4(b[2 * jp][0], b[2 * jp + 1][0], b[2 * jp][1], b[2 * jp + 1][1],
                      bh + jp * 16 * 80);
            #pragma unroll
            for (int i = 0; i < 2; ++i)
                #pragma unroll
                for (int jj = 0; jj < NJJ; ++jj)
                    mma16816(c[i][jj], a[i], b[jj]);
        }
    }
}

// epilogue: relu(c+bias) -> bf16 hi/lo H tiles; clears c
__device__ __forceinline__ void epi_to_H(float (&c)[2][4][4], const float* bias,
                                         char* smem, int warp_m, int warp_n, int lane) {
    __syncthreads();
    #pragma unroll
    for (int i = 0; i < 2; ++i) {
        #pragma unroll
        for (int jj = 0; jj < 4; ++jj) {
            int col = warp_n * 32 + jj * 8 + (lane & 3) * 2;
            int ch = col >> 5, kk = col & 31;
            float b0 = __ldg(&bias[col]), b1 = __ldg(&bias[col + 1]);
            #pragma unroll
            for (int rh = 0; rh < 2; ++rh) {
                int row = warp_m * 32 + i * 16 + (lane >> 2) + rh * 8;
                float v0 = fmaxf(c[i][jj][rh * 2 + 0] + b0, 0.f);
                float v1 = fmaxf(c[i][jj][rh * 2 + 1] + b1, 0.f);
                float l0 = v0 - __bfloat162float(__float2bfloat16_rn(v0));
                float l1 = v1 - __bfloat162float(__float2bfloat16_rn(v1));
                *(uint32_t*)(smem + OFF_H + (ch * 2 + 0) * PLANE_A + (row * SP + kk) * 2) = bf2pack(v0, v1);
                *(uint32_t*)(smem + OFF_H + (ch * 2 + 1) * PLANE_A + (row * SP + kk) * 2) = bf2pack(l0, l1);
                c[i][jj][rh * 2 + 0] = 0.f;
                c[i][jj][rh * 2 + 1] = 0.f;
            }
        }
    }
}

__global__ void __launch_bounds__(256, 2) k_fused(
    const float* __restrict__ train, const __nv_bfloat16* __restrict__ aggb,
    const __nv_bfloat16* __restrict__ wtb,
    const float* __restrict__ b1, const float* __restrict__ b2,
    const float* __restrict__ bc1, const float* __restrict__ bc2,
    float* __restrict__ outp)
{
    extern __shared__ __align__(16) char smem[];
    const int tid    = threadIdx.x;
    const int lane   = tid & 31;
    const int wid    = tid >> 5;
    const int warp_m = wid >> 2;     // 0..1 -> 32-row band
    const int warp_n = wid & 3;      // 0..3 -> 32-col band
    const int m0     = blockIdx.x * MT;

    const uint32_t sb    = smem_u32(smem);
    const uint32_t ast_u = sb + OFF_AST;
    const uint32_t bs_u  = sb + OFF_BS;
    const uint32_t afp_u = sb + OFF_AFP;
    float* Afp = (float*)(smem + OFF_AFP);

    float c[2][4][4];
    #pragma unroll
    for (int i = 0; i < 2; ++i)
        #pragma unroll
        for (int j = 0; j < 4; ++j)
            #pragma unroll
            for (int q = 0; q < 4; ++q) c[i][j][q] = 0.f;

    // B loads for chunk cj into stage (always commits one group)
    auto issue_B = [&](int cj, int stage) {
        Desc d = mkdesc(cj, wtb);
        #pragma unroll
        for (int p = 0; p < 2; ++p) {
            const __nv_bfloat16* bp = d.B + (size_t)p * 128 * 512;
            uint32_t bd = bs_u + (stage * 2 + p) * PLANE_B;
            #pragma unroll
            for (int i = 0; i < 2; ++i) {
                int idx = i * 256 + tid;
                int n = idx >> 2, cc = idx & 3;
                CP16(bd + n * 80 + cc * 16, bp + (size_t)n * 512 + d.bk0 + cc * 8);
            }
        }
        CP_COMMIT();
    };
    // A loads for chunk cj (always commits one group, possibly empty)
    auto issue_A = [&](int cj, int stage) {
        Desc d = mkdesc(cj, wtb);
        if (d.mode == 1) {
            #pragma unroll
            for (int i = 0; i < 2; ++i) {
                int idx = i * 256 + tid;
                int row = idx >> 3, cc = idx & 7;
                int gr = m0 + row, k = d.k0 + cc * 4;
                int nb = 0;
                if (gr < NT) { int rem = DST_DIM - k; nb = (rem >= 4) ? 16 : (rem > 0 ? rem * 4 : 0); }
                const float* src = nb ? (train + (size_t)gr * DST_DIM + k) : train;
                CP16Z(afp_u + row * 144 + cc * 16, src, nb);
            }
        } else if (d.mode == 2) {
            #pragma unroll
            for (int i = 0; i < 2; ++i) {
                int idx = i * 256 + tid;
                int plane = idx >> 8;
                int rem = idx & 255;
                int row = rem >> 2, cc = rem & 3;
                int gr = m0 + row;
                uint32_t dst = ast_u + (stage * 2 + plane) * PLANE_A + row * 80 + cc * 16;
                const __nv_bfloat16* src =
                    aggb + (size_t)plane * NT * 128 + (size_t)gr * 128 + d.k0 + cc * 8;
                int nb = (gr < NT) ? 16 : 0;
                CP16Z(dst, nb ? src : (const __nv_bfloat16*)aggb, nb);
            }
        }
        CP_COMMIT();
    };

    // prologue: chunk 0 fully issued (B then A)
    issue_B(0, 0);
    issue_A(0, 0);

    for (int j = 0; j < 36; ++j) {
        const int s = j & 1;
        Desc d = mkdesc(j, wtb);

        // 1. early-issue next chunk's B into the other stage
        if (j + 1 < 36) issue_B(j + 1, s ^ 1);

        // 2. wait: chunk j's groups resident; chunk j+1's B may stay in flight
        if (j + 1 < 36) { CP_WAITG1(); } else { CP_WAIT0(); }
        __syncthreads();

        // 3. convert fp32 staging -> bf16 hi/lo Ast[s] (train chunks; 4 threads/row)
        if (d.mode == 1) {
            {
                int row = tid >> 2, qtr = tid & 3;
                __nv_bfloat16* Ah = (__nv_bfloat16*)(smem + OFF_AST + (s * 2 + 0) * PLANE_A);
                __nv_bfloat16* Al = (__nv_bfloat16*)(smem + OFF_AST + (s * 2 + 1) * PLANE_A);
                const float* ar = Afp + row * 36 + qtr * 8;
                uint32_t hp[4], lp[4];
                #pragma unroll
                for (int cc = 0; cc < 2; ++cc) {
                    float4 f = *(const float4*)(ar + cc * 4);
                    float l0 = f.x - __bfloat162float(__float2bfloat16_rn(f.x));
                    float l1 = f.y - __bfloat162float(__float2bfloat16_rn(f.y));
                    float l2 = f.z - __bfloat162float(__float2bfloat16_rn(f.z));
                    float l3 = f.w - __bfloat162float(__float2bfloat16_rn(f.w));
                    hp[cc * 2 + 0] = bf2pack(f.x, f.y);
                    hp[cc * 2 + 1] = bf2pack(f.z, f.w);
                    lp[cc * 2 + 0] = bf2pack(l0, l1);
                    lp[cc * 2 + 1] = bf2pack(l2, l3);
                }
                *(uint4*)((uint32_t*)(Ah + row * SP + qtr * 8)) = *(uint4*)hp;
                *(uint4*)((uint32_t*)(Al + row * SP + qtr * 8)) = *(uint4*)lp;
            }
            __syncthreads();   // Ast[s] ready; AFP free for next issue_A
        }

        // 4. issue next chunk's A
        if (j + 1 < 36) issue_A(j + 1, s ^ 1);

        // 5. MMA on chunk j
        const uint32_t Ab = (d.mode != 0) ? (ast_u + s * 2 * PLANE_A)
                                          : (sb + OFF_H + d.hch * 2 * PLANE_A);
        const uint32_t Bb = bs_u + s * 2 * PLANE_B;
        if (j < 32)           mma_chunk<4>(Ab, Bb, warp_m, warp_n, lane, c);
        else if (warp_n == 0) mma_chunk<2>(Ab, Bb, warp_m, warp_n, lane, c);

        if (j == 19)      epi_to_H(c, b1, smem, warp_m, warp_n, lane);
        else if (j == 27) epi_to_H(c, b2, smem, warp_m, warp_n, lane);
        else if (j == 31) epi_to_H(c, bc1, smem, warp_m, warp_n, lane);

        // 6. protect stage s for the early issue at top of iteration j+1
        __syncthreads();
    }

    // ---- cls store: out[NT,16] = c + bc2 (warp_n==0 warps hold cols 0..15) ----
    if (warp_n == 0) {
        #pragma unroll
        for (int i = 0; i < 2; ++i) {
            #pragma unroll
            for (int jj = 0; jj < 2; ++jj) {
                int col = jj * 8 + (lane & 3) * 2;
                float b0 = __ldg(&bc2[col]), b1 = __ldg(&bc2[col + 1]);
                #pragma unroll
                for (int rh = 0; rh < 2; ++rh) {
                    int row = m0 + warp_m * 32 + i * 16 + (lane >> 2) + rh * 8;
                    if (row < NT) {
                        float2 v = make_float2(c[i][jj][rh * 2 + 0] + b0,
                                               c[i][jj][rh * 2 + 1] + b1);
                        *(float2*)(outp + (size_t)row * NCLS + col) = v;
                    }
                }
            }
        }
    }
}

// ---------------- launch ----------------
extern "C" void kernel_launch(void* const* d_in, const int* in_sizes, int n_in,
                              void* d_out, int out_size)
{
    const float* gene  = (const float*)d_in[0];
    const float* train = (const float*)d_in[1];
    const int*   esrc  = (const int*)  d_in[2];
    const int*   edst  = (const int*)  d_in[3];
    const float* W1n   = (const float*)d_in[4];
    const float* W1s   = (const float*)d_in[5];
    const float* b1    = (const float*)d_in[6];
    const float* W2n   = (const float*)d_in[7];
    const float* W2s   = (const float*)d_in[8];
    const float* b2    = (const float*)d_in[9];
    const float* Wc1   = (const float*)d_in[10];
    const float* bc1   = (const float*)d_in[11];
    const float* Wc2   = (const float*)d_in[12];
    const float* bc2   = (const float*)d_in[13];
    float* out = (float*)d_out;

    __nv_bfloat16 *wtb, *aggb;
    cudaGetSymbolAddress((void**)&wtb,  g_wtb);
    cudaGetSymbolAddress((void**)&aggb, g_aggb);

    static bool attr_done = false;
    if (!attr_done) {
        cudaFuncSetAttribute(k_fused, cudaFuncAttributeMaxDynamicSharedMemorySize, SMEM_FUSED);
        cudaFuncSetAttribute(k_fused, cudaFuncAttributePreferredSharedMemoryCarveout,
                             cudaSharedmemCarveoutMaxShared);
        attr_done = true;
    }

    k_trh<<<(6 * 65536 + 255) / 256, 256>>>(W1s, W1n, W2s, W2n, Wc1, Wc2, edst);
    k_scan<<<1, 1024>>>();
    k_scatter<<<(NE / 8 + 255) / 256, 256>>>(esrc, edst);
    k_spmm<<<(NT * 32 + 255) / 256, 256>>>(gene);
    k_fused<<<(NT + MT - 1) / MT, 256, SMEM_FUSED>>>(train, aggb, wtb, b1, b2, bc1, bc2, out);

    (void)in_sizes; (void)n_in; (void)out_size;
}